// round 2
// baseline (speedup 1.0000x reference)
#include <cuda_runtime.h>

#define NT  128   // threads (one block, persistent)
#define FPT 4     // frequencies per thread: 128*4 = 512

__global__ void __launch_bounds__(NT, 1)
sgd_filter_design_kernel(const float* __restrict__ sos_init,
                         const float* __restrict__ target_dB,
                         float* __restrict__ out)
{
    __shared__ float sos[96];        // [16 sections][b0 b1 b2 a0 a1 a2]
    __shared__ float part[4][96];    // per-warp gradient partials

    const int tid  = threadIdx.x;
    const int warp = tid >> 5;
    const int lane = tid & 31;

    if (tid < 96) sos[tid] = sos_init[tid];

    // Per-thread frequency constants (computed once, in double for accuracy).
    float c1[FPT], s1[FPT], c2[FPT], s2[FPT], tgt[FPT];
#pragma unroll
    for (int f = 0; f < FPT; ++f) {
        int i = tid + f * NT;                       // freq index 0..511
        double w = (double)i * (3.14159265358979323846 / 511.0); // linspace(0,pi,512)
        c1[f] = (float)cos(w);
        s1[f] = (float)sin(w);
        c2[f] = (float)cos(2.0 * w);
        s2[f] = (float)sin(2.0 * w);
        tgt[f] = target_dB[i];
    }
    __syncthreads();

    const float KC  = 40.0f / (512.0f * 2.30258509299404568402f); // 2/n * 20/ln10
    const float EPS = 1e-8f;
    const float LR  = 0.1f;

    for (int it = 0; it < 1000; ++it) {
        // ---------- Pass 1: |H|^2 per frequency, ratio accumulated per section
        // (matches reference's prod(B/A): keeps intermediates O(1), no underflow)
        float pR[FPT];
#pragma unroll
        for (int f = 0; f < FPT; ++f) pR[f] = 1.0f;

        for (int s = 0; s < 16; ++s) {            // rolled: keep body small
            float b0 = sos[s*6+0], b1 = sos[s*6+1], b2 = sos[s*6+2];
            float a0 = sos[s*6+3], a1 = sos[s*6+4], a2 = sos[s*6+5];
#pragma unroll
            for (int f = 0; f < FPT; ++f) {
                float Br = fmaf(b2, c2[f], fmaf(b1, c1[f], b0));
                float Bi = -fmaf(b2, s2[f], b1 * s1[f]);
                float Ar = fmaf(a2, c2[f], fmaf(a1, c1[f], a0));
                float Ai = -fmaf(a2, s2[f], a1 * s1[f]);
                pR[f] *= fmaf(Br, Br, Bi * Bi) / fmaf(Ar, Ar, Ai * Ai);
            }
        }

        // c_i = KC * (dB_i - t_i) * mag/(mag+eps)
        float cc[FPT];
#pragma unroll
        for (int f = 0; f < FPT; ++f) {
            float mag = sqrtf(pR[f]);
            float mpe = mag + EPS;
            float dB  = 20.0f * log10f(mpe);
            cc[f] = KC * (dB - tgt[f]) * (mag / mpe);
        }

        // ---------- Pass 2: per-section gradients + reduction ----------
        for (int s = 0; s < 16; ++s) {
            float b0 = sos[s*6+0], b1 = sos[s*6+1], b2 = sos[s*6+2];
            float a0 = sos[s*6+3], a1 = sos[s*6+4], a2 = sos[s*6+5];
            float g0 = 0.f, g1 = 0.f, g2 = 0.f, g3 = 0.f, g4 = 0.f, g5 = 0.f;
#pragma unroll
            for (int f = 0; f < FPT; ++f) {
                float Br = fmaf(b2, c2[f], fmaf(b1, c1[f], b0));
                float Bi = -fmaf(b2, s2[f], b1 * s1[f]);
                float Ar = fmaf(a2, c2[f], fmaf(a1, c1[f], a0));
                float Ai = -fmaf(a2, s2[f], a1 * s1[f]);
                float cB = cc[f] / fmaf(Br, Br, Bi * Bi);
                float cA = cc[f] / fmaf(Ar, Ar, Ai * Ai);
                g0 = fmaf(cB, Br, g0);
                g1 = fmaf(cB, fmaf(c1[f], Br, -s1[f] * Bi), g1);
                g2 = fmaf(cB, fmaf(c2[f], Br, -s2[f] * Bi), g2);
                g3 = fmaf(-cA, Ar, g3);
                g4 = fmaf(-cA, fmaf(c1[f], Ar, -s1[f] * Ai), g4);
                g5 = fmaf(-cA, fmaf(c2[f], Ar, -s2[f] * Ai), g5);
            }
            // deterministic warp tree reduction
#pragma unroll
            for (int o = 16; o > 0; o >>= 1) {
                g0 += __shfl_xor_sync(0xffffffffu, g0, o);
                g1 += __shfl_xor_sync(0xffffffffu, g1, o);
                g2 += __shfl_xor_sync(0xffffffffu, g2, o);
                g3 += __shfl_xor_sync(0xffffffffu, g3, o);
                g4 += __shfl_xor_sync(0xffffffffu, g4, o);
                g5 += __shfl_xor_sync(0xffffffffu, g5, o);
            }
            if (lane == 0) {
                part[warp][s*6+0] = g0;
                part[warp][s*6+1] = g1;
                part[warp][s*6+2] = g2;
                part[warp][s*6+3] = g3;
                part[warp][s*6+4] = g4;
                part[warp][s*6+5] = g5;
            }
        }
        __syncthreads();
        if (tid < 96) {
            float g = (part[0][tid] + part[1][tid]) + (part[2][tid] + part[3][tid]);
            sos[tid] -= LR * g;
        }
        __syncthreads();
    }

    if (tid < 96) out[tid] = sos[tid];
}

extern "C" void kernel_launch(void* const* d_in, const int* in_sizes, int n_in,
                              void* d_out, int out_size) {
    const float* sos_init  = (const float*)d_in[0];   // [16,6] = 96 floats
    const float* target_dB = (const float*)d_in[1];   // [512]
    float* out = (float*)d_out;                       // [16,6] = 96 floats
    sgd_filter_design_kernel<<<1, NT>>>(sos_init, target_dB, out);
}

// round 3
// speedup vs baseline: 3.2730x; 3.2730x over previous
#include <cuda_runtime.h>

#define NT 512   // 16 warps, one block, one SM

__device__ __forceinline__ float frcp(float x) {
    float r; asm("rcp.approx.f32 %0, %1;" : "=f"(r) : "f"(x)); return r;
}

__global__ void __launch_bounds__(NT, 1)
sgd_filter_design_kernel(const float* __restrict__ sos_init,
                         const float* __restrict__ target_dB,
                         float* __restrict__ out)
{
    __shared__ float  sos[16][8];   // [section][coef], padded row
    __shared__ float4 trig[512];    // (cos w, sin w, cos 2w, sin 2w) per freq
    __shared__ float  ccs[512];     // per-freq weight c_i
    __shared__ float  grad[96];     // final per-parameter gradient

    const int tid  = threadIdx.x;
    const int warp = tid >> 5;
    const int lane = tid & 31;

    if (tid < 96) sos[tid / 6][tid % 6] = sos_init[tid];

    // Per-freq constants (thread tid owns freq tid). Double-precision trig once.
    float tc1, ts1, tc2, ts2, tgt;
    {
        double w = (double)tid * (3.14159265358979323846 / 511.0);
        tc1 = (float)cos(w);        ts1 = (float)sin(w);
        tc2 = (float)cos(2.0 * w);  ts2 = (float)sin(2.0 * w);
        trig[tid] = make_float4(tc1, ts1, tc2, ts2);
        tgt = target_dB[tid];
    }
    __syncthreads();

    const float KC  = 40.0f / (512.0f * 2.30258509299404568402f); // 2/n * 20/ln10
    const float EPS = 1e-8f;
    const float LR  = 0.1f;

    for (int it = 0; it < 1000; ++it) {
        // ---------- Pass 1 (freq-parallel): mag ratio product + per-freq weight
        float pR = 1.0f;
#pragma unroll
        for (int s = 0; s < 16; ++s) {
            float b0 = sos[s][0], b1 = sos[s][1], b2 = sos[s][2];
            float a0 = sos[s][3], a1 = sos[s][4], a2 = sos[s][5];
            float Br = fmaf(b2, tc2, fmaf(b1, tc1, b0));
            float Bi = -fmaf(b2, ts2, b1 * ts1);
            float Ar = fmaf(a2, tc2, fmaf(a1, tc1, a0));
            float Ai = -fmaf(a2, ts2, a1 * ts1);
            pR *= fmaf(Br, Br, Bi * Bi) * frcp(fmaf(Ar, Ar, Ai * Ai));
        }
        {
            float mag = sqrtf(pR);
            float mpe = mag + EPS;
            float dB  = 20.0f * log10f(mpe);
            ccs[tid] = KC * (dB - tgt) * (mag * frcp(mpe));
        }
        __syncthreads();

        // ---------- Pass 2 (section-parallel): warp s owns section s ----------
        {
            const int s = warp;
            float b0 = sos[s][0], b1 = sos[s][1], b2 = sos[s][2];
            float a0 = sos[s][3], a1 = sos[s][4], a2 = sos[s][5];
            float g0 = 0.f, g1 = 0.f, g2 = 0.f, g3 = 0.f, g4 = 0.f, g5 = 0.f;
#pragma unroll
            for (int k = 0; k < 16; ++k) {
                int f = k * 32 + lane;
                float4 t = trig[f];
                float  c = ccs[f];
                float Br = fmaf(b2, t.z, fmaf(b1, t.x, b0));
                float Bi = -fmaf(b2, t.w, b1 * t.y);
                float Ar = fmaf(a2, t.z, fmaf(a1, t.x, a0));
                float Ai = -fmaf(a2, t.w, a1 * t.y);
                float cB =  c * frcp(fmaf(Br, Br, Bi * Bi));
                float cA = -c * frcp(fmaf(Ar, Ar, Ai * Ai));
                g0 = fmaf(cB, Br, g0);
                g1 = fmaf(cB, fmaf(t.x, Br, -t.y * Bi), g1);
                g2 = fmaf(cB, fmaf(t.z, Br, -t.w * Bi), g2);
                g3 = fmaf(cA, Ar, g3);
                g4 = fmaf(cA, fmaf(t.x, Ar, -t.y * Ai), g4);
                g5 = fmaf(cA, fmaf(t.z, Ar, -t.w * Ai), g5);
            }
            // single deterministic butterfly tree per warp (30 SHFLs)
#pragma unroll
            for (int o = 16; o > 0; o >>= 1) {
                g0 += __shfl_xor_sync(0xffffffffu, g0, o);
                g1 += __shfl_xor_sync(0xffffffffu, g1, o);
                g2 += __shfl_xor_sync(0xffffffffu, g2, o);
                g3 += __shfl_xor_sync(0xffffffffu, g3, o);
                g4 += __shfl_xor_sync(0xffffffffu, g4, o);
                g5 += __shfl_xor_sync(0xffffffffu, g5, o);
            }
            if (lane == 0) {
                grad[s * 6 + 0] = g0;
                grad[s * 6 + 1] = g1;
                grad[s * 6 + 2] = g2;
                grad[s * 6 + 3] = g3;
                grad[s * 6 + 4] = g4;
                grad[s * 6 + 5] = g5;
            }
        }
        __syncthreads();

        // ---------- SGD update ----------
        if (tid < 96) sos[tid / 6][tid % 6] -= LR * grad[tid];
        __syncthreads();
    }

    if (tid < 96) out[tid] = sos[tid / 6][tid % 6];
}

extern "C" void kernel_launch(void* const* d_in, const int* in_sizes, int n_in,
                              void* d_out, int out_size) {
    const float* sos_init  = (const float*)d_in[0];   // [16,6] = 96 floats
    const float* target_dB = (const float*)d_in[1];   // [512]
    float* out = (float*)d_out;                       // [16,6] = 96 floats
    sgd_filter_design_kernel<<<1, NT>>>(sos_init, target_dB, out);
}

// round 4
// speedup vs baseline: 4.3252x; 1.3215x over previous
#include <cuda_runtime.h>
#include <cstdint>

#define NT      512   // threads per CTA (16 warps)
#define CLUSTER 4     // CTAs per cluster; freqs split 128/CTA

__device__ __forceinline__ float frcp(float x) {
    float r; asm("rcp.approx.f32 %0, %1;" : "=f"(r) : "f"(x)); return r;
}
__device__ __forceinline__ uint32_t smem_u32(const void* p) {
    uint32_t a;
    asm("{ .reg .u64 t; cvta.to.shared.u64 t, %1; cvt.u32.u64 %0, t; }" : "=r"(a) : "l"(p));
    return a;
}
__device__ __forceinline__ uint32_t my_rank() {
    uint32_t r; asm("mov.u32 %0, %%cluster_ctarank;" : "=r"(r)); return r;
}
__device__ __forceinline__ void st_cluster_f32(uint32_t local_addr, uint32_t rank, float v) {
    uint32_t remote;
    asm volatile("mapa.shared::cluster.u32 %0, %1, %2;" : "=r"(remote) : "r"(local_addr), "r"(rank));
    asm volatile("st.shared::cluster.f32 [%0], %1;" :: "r"(remote), "f"(v) : "memory");
}
__device__ __forceinline__ void cluster_sync() {
    asm volatile("barrier.cluster.arrive.aligned;" ::: "memory");
    asm volatile("barrier.cluster.wait.aligned;" ::: "memory");
}

__global__ void __launch_bounds__(NT, 1) __cluster_dims__(CLUSTER, 1, 1)
sgd_filter_design_kernel(const float* __restrict__ sos_init,
                         const float* __restrict__ target_dB,
                         float* __restrict__ out)
{
    __shared__ float  sos[16][8];       // replicated filter state
    __shared__ float4 trig[128];        // this CTA's 128 freqs: (c1,s1,c2,s2)
    __shared__ float  ccs[128];         // per-freq weight c_i (local freqs)
    __shared__ float  part[2][CLUSTER][96]; // double-buffered cross-CTA grad partials

    const int tid  = threadIdx.x;
    const int warp = tid >> 5;
    const int lane = tid & 31;
    const int q    = tid >> 2;          // local freq 0..127
    const int g    = tid & 3;           // section group (4 sections each)
    const uint32_t rank = my_rank();

    if (tid < 96) sos[tid / 6][tid % 6] = sos_init[tid];

    // Per-thread trig for freq q (global index rank*128+q), double precision once.
    float tc1, ts1, tc2, ts2, tgt;
    {
        int gf = (int)rank * 128 + q;
        double w = (double)gf * (3.14159265358979323846 / 511.0);
        tc1 = (float)cos(w);        ts1 = (float)sin(w);
        tc2 = (float)cos(2.0 * w);  ts2 = (float)sin(2.0 * w);
        if (g == 0) trig[q] = make_float4(tc1, ts1, tc2, ts2);
        tgt = target_dB[gf];
    }
    __syncthreads();
    cluster_sync();   // all CTAs initialized before any DSMEM traffic

    const float KC  = 40.0f / (512.0f * 2.30258509299404568402f); // 2/n * 20/ln10
    const float EPS = 1e-8f;
    const float LR  = 0.1f;

    for (int it = 0; it < 1000; ++it) {
        // ---- Pass 1 (local): full |H| product; sections split across 4 lanes ----
        float pP = 1.0f;
#pragma unroll
        for (int j = 0; j < 4; ++j) {
            int s = g * 4 + j;
            float b0 = sos[s][0], b1 = sos[s][1], b2 = sos[s][2];
            float a0 = sos[s][3], a1 = sos[s][4], a2 = sos[s][5];
            float Br = fmaf(b2, tc2, fmaf(b1, tc1, b0));
            float Bi = -fmaf(b2, ts2, b1 * ts1);
            float Ar = fmaf(a2, tc2, fmaf(a1, tc1, a0));
            float Ai = -fmaf(a2, ts2, a1 * ts1);
            pP *= fmaf(Br, Br, Bi * Bi) * frcp(fmaf(Ar, Ar, Ai * Ai));
        }
        // combine the 4 per-lane partial products (lanes of same freq are adjacent)
        pP *= __shfl_xor_sync(0xffffffffu, pP, 1);
        pP *= __shfl_xor_sync(0xffffffffu, pP, 2);
        {
            float mag = sqrtf(pP);
            float mpe = mag + EPS;
            float dB  = 20.0f * log10f(mpe);
            float cc  = KC * (dB - tgt) * (mag * frcp(mpe));
            if (g == 0) ccs[q] = cc;
        }
        __syncthreads();

        // ---- Pass 2: warp s integrates section s over this CTA's 128 freqs ----
        {
            const int s = warp;
            float b0 = sos[s][0], b1 = sos[s][1], b2 = sos[s][2];
            float a0 = sos[s][3], a1 = sos[s][4], a2 = sos[s][5];
            float g0 = 0.f, g1 = 0.f, g2 = 0.f, g3 = 0.f, g4 = 0.f, g5 = 0.f;
#pragma unroll
            for (int k = 0; k < 4; ++k) {
                int f = k * 32 + lane;
                float4 t = trig[f];
                float  c = ccs[f];
                float Br = fmaf(b2, t.z, fmaf(b1, t.x, b0));
                float Bi = -fmaf(b2, t.w, b1 * t.y);
                float Ar = fmaf(a2, t.z, fmaf(a1, t.x, a0));
                float Ai = -fmaf(a2, t.w, a1 * t.y);
                float cB =  c * frcp(fmaf(Br, Br, Bi * Bi));
                float cA = -c * frcp(fmaf(Ar, Ar, Ai * Ai));
                g0 = fmaf(cB, Br, g0);
                g1 = fmaf(cB, fmaf(t.x, Br, -t.y * Bi), g1);
                g2 = fmaf(cB, fmaf(t.z, Br, -t.w * Bi), g2);
                g3 = fmaf(cA, Ar, g3);
                g4 = fmaf(cA, fmaf(t.x, Ar, -t.y * Ai), g4);
                g5 = fmaf(cA, fmaf(t.z, Ar, -t.w * Ai), g5);
            }
#pragma unroll
            for (int o = 16; o > 0; o >>= 1) {
                g0 += __shfl_xor_sync(0xffffffffu, g0, o);
                g1 += __shfl_xor_sync(0xffffffffu, g1, o);
                g2 += __shfl_xor_sync(0xffffffffu, g2, o);
                g3 += __shfl_xor_sync(0xffffffffu, g3, o);
                g4 += __shfl_xor_sync(0xffffffffu, g4, o);
                g5 += __shfl_xor_sync(0xffffffffu, g5, o);
            }
            // all lanes hold the sums; lanes 0..3 scatter this CTA's partial
            // (slot [rank]) into CTA 'lane' via DSMEM
            if (lane < CLUSTER) {
                uint32_t base = smem_u32(&part[it & 1][rank][s * 6]);
                st_cluster_f32(base +  0, (uint32_t)lane, g0);
                st_cluster_f32(base +  4, (uint32_t)lane, g1);
                st_cluster_f32(base +  8, (uint32_t)lane, g2);
                st_cluster_f32(base + 12, (uint32_t)lane, g3);
                st_cluster_f32(base + 16, (uint32_t)lane, g4);
                st_cluster_f32(base + 20, (uint32_t)lane, g5);
            }
        }
        cluster_sync();   // all partials visible everywhere (arrive = release)

        // ---- SGD update (replicated, fixed summation order) ----
        if (tid < 96) {
            const float* p0 = part[it & 1][0];
            const float* p1 = part[it & 1][1];
            const float* p2 = part[it & 1][2];
            const float* p3 = part[it & 1][3];
            float gr = (p0[tid] + p1[tid]) + (p2[tid] + p3[tid]);
            sos[tid / 6][tid % 6] -= LR * gr;
        }
        __syncthreads();
    }

    if (rank == 0 && tid < 96) out[tid] = sos[tid / 6][tid % 6];
}

extern "C" void kernel_launch(void* const* d_in, const int* in_sizes, int n_in,
                              void* d_out, int out_size) {
    const float* sos_init  = (const float*)d_in[0];   // [16,6] = 96 floats
    const float* target_dB = (const float*)d_in[1];   // [512]
    float* out = (float*)d_out;                       // [16,6] = 96 floats
    sgd_filter_design_kernel<<<CLUSTER, NT>>>(sos_init, target_dB, out);
}